// round 1
// baseline (speedup 1.0000x reference)
#include <cuda_runtime.h>
#include <math.h>

// ---------------------------------------------------------------------------
// Problem constants: B=8, C=256, H=W=128, M=7
// ---------------------------------------------------------------------------
#define NIMG   2048          // B*C
#define PI_F   3.14159265358979323846f

// Scratch (device globals; allocation-free per harness rules)
__device__ float g_b0r[33554432];
__device__ float g_b0i[33554432];
__device__ float g_b1r[33554432];
__device__ float g_b1i[33554432];
__device__ float g_mag[8 * 49];
__device__ float g_kern[8 * 49];

// ---------------------------------------------------------------------------
// Per-warp 128-point Stockham FFT in shared memory.
// Input in wsA, result in wsB (natural order). INV => e^{+i} (unnormalized).
// ---------------------------------------------------------------------------
template<bool INV>
__device__ __forceinline__ void warp_fft128(float2* wsA, float2* wsB, int lane)
{
    float2* s = wsA;
    float2* d = wsB;
    int m = 1;
    const float sgn = INV ? (PI_F / 64.f) : (-PI_F / 64.f);
#pragma unroll
    for (int st = 0; st < 7; ++st) {
        __syncwarp();
#pragma unroll
        for (int uu = 0; uu < 2; ++uu) {
            int u  = lane + uu * 32;
            int jm = u & ~(m - 1);         // j*m, also twiddle index
            float2 a = s[u];
            float2 b = s[u + 64];
            float ang = sgn * (float)jm;   // +- pi * j / l
            float sw, cw;
            __sincosf(ang, &sw, &cw);
            float dx = a.x - b.x;
            float dy = a.y - b.y;
            d[u + jm]     = make_float2(a.x + b.x, a.y + b.y);
            d[u + jm + m] = make_float2(dx * cw - dy * sw, dx * sw + dy * cw);
        }
        float2* t = s; s = d; d = t;
        m <<= 1;
    }
    __syncwarp();
}

// staging swizzle: kills the 32-way conflict of column writes
#define STG(f, rl) ((f) * 32 + (((rl) ^ (f)) & 31))

// ---------------------------------------------------------------------------
// Generic FFT pass with transposed output.
// Input : in[img][row][0..127]  (contiguous innermost)
// Output: out[img][f][row]      (transposed, contiguous in 'row')
//   SHIFT_IN : read element (idx^64)  -> ifftshift of the transform axis
//   SHIFT_OUT: store freq at (f^64)   -> fftshift of the transform axis
// Block: 8 warps, handles 32 rows (blockIdx.x = img*4 + rowgroup)
// ---------------------------------------------------------------------------
template<bool INV, bool SHIFT_IN, bool SHIFT_OUT, bool IN_REAL, bool OUT_REAL>
__global__ void __launch_bounds__(256)
fft_pass(const float* __restrict__ in_r, const float* __restrict__ in_i,
         float* __restrict__ out_r, float* __restrict__ out_i, float scale)
{
    __shared__ float2 s_ws[8 * 256];      // per-warp ping-pong (16 KB)
    __shared__ float2 s_stage[128 * 32];  // transpose staging   (32 KB)

    const int tid  = threadIdx.x;
    const int warp = tid >> 5;
    const int lane = tid & 31;
    const int img  = blockIdx.x >> 2;
    const int grp  = blockIdx.x & 3;
    const size_t ibase = (size_t)img * (128 * 128);

    float2* wsA = s_ws + warp * 256;
    float2* wsB = wsA + 128;

    for (int q = 0; q < 4; ++q) {
        const int rl  = warp * 4 + q;       // local row 0..31
        const int row = grp * 32 + rl;      // global row
        const float* pr = in_r + ibase + (size_t)row * 128;
        const float* pi = IN_REAL ? nullptr : (in_i + ibase + (size_t)row * 128);
#pragma unroll
        for (int k = 0; k < 4; ++k) {
            int idx = lane + k * 32;
            int pos = SHIFT_IN ? (idx ^ 64) : idx;
            float vr = pr[pos] * scale;
            float vi = IN_REAL ? 0.f : pi[pos] * scale;
            wsA[idx] = make_float2(vr, vi);
        }
        warp_fft128<INV>(wsA, wsB, lane);
#pragma unroll
        for (int k = 0; k < 4; ++k) {
            int idx = lane + k * 32;
            int fp  = SHIFT_OUT ? (idx ^ 64) : idx;
            s_stage[STG(fp, rl)] = wsB[idx];
        }
    }
    __syncthreads();

    const int g0 = grp * 32;
#pragma unroll
    for (int it = 0; it < 16; ++it) {
        int idx = it * 256 + tid;           // 0..4095
        int f   = idx >> 5;
        int rl  = idx & 31;
        float2 v = s_stage[STG(f, rl)];
        size_t o = ibase + (size_t)f * 128 + (g0 + rl);
        out_r[o] = v.x;
        if (!OUT_REAL) out_i[o] = v.y;
    }
}

// ---------------------------------------------------------------------------
// mag_center: mean over channels of |S| at the 7x7 center of the shifted
// spectrum. One block per batch, thread = channel.
// ---------------------------------------------------------------------------
__global__ void __launch_bounds__(256)
mag_kernel(const float* __restrict__ Sr, const float* __restrict__ Si,
           float* __restrict__ mag)
{
    const int b = blockIdx.x;
    const int c = threadIdx.x;
    __shared__ float red[256];
    for (int i = 0; i < 49; ++i) {
        int dy = i / 7, dx = i % 7;
        size_t o = (((size_t)(b * 256 + c) * 128) + 61 + dy) * 128 + (61 + dx);
        float r = Sr[o], im = Si[o];
        red[c] = sqrtf(r * r + im * im);
        __syncthreads();
        for (int s = 128; s > 0; s >>= 1) {
            if (c < s) red[c] += red[c + s];
            __syncthreads();
        }
        if (c == 0) mag[b * 49 + i] = red[0] * (1.f / 256.f);
        __syncthreads();
    }
}

// ---------------------------------------------------------------------------
// MLP (49->32->3) + anisotropic kernel generation. One warp per batch.
// ---------------------------------------------------------------------------
__global__ void __launch_bounds__(256)
mlp_kernel(const float* __restrict__ w1, const float* __restrict__ b1,
           const float* __restrict__ w2, const float* __restrict__ b2,
           const float* __restrict__ mag, float* __restrict__ kern)
{
    const int tid  = threadIdx.x;
    const int b    = tid >> 5;
    const int lane = tid & 31;
    __shared__ float sh_h[8][32];
    __shared__ float sp[8][3];

    float h = b1[lane];
    for (int i = 0; i < 49; ++i) h += mag[b * 49 + i] * w1[lane * 49 + i];
    h = fmaxf(h, 0.f);
    sh_h[b][lane] = h;
    __syncthreads();

    if (lane < 3) {
        float p = b2[lane];
        for (int j = 0; j < 32; ++j) p += sh_h[b][j] * w2[lane * 32 + j];
        sp[b][lane] = p;
    }
    __syncthreads();

    float p0 = sp[b][0], p1 = sp[b][1], p2 = sp[b][2];
    float theta = atan2f(p0, p1) * 0.5f + PI_F * 0.5f;
    float lam1  = expf(p2);
    float lam2  = 1.f / (lam1 + 1e-8f);
    float ct = cosf(theta), st = sinf(theta);
    float inv1 = 1.f / (2.f * lam1 * lam1);
    float inv2 = 1.f / (2.f * lam2 * lam2);

    float v0 = 0.f, v1 = 0.f;
    {
        int idx = lane;
        float yy = (float)(idx / 7) - 3.f;
        float xx = (float)(idx % 7) - 3.f;
        float xr =  xx * ct + yy * st;
        float yr = -xx * st + yy * ct;
        v0 = expf(-(xr * xr * inv1 + yr * yr * inv2));
    }
    {
        int idx = lane + 32;
        if (idx < 49) {
            float yy = (float)(idx / 7) - 3.f;
            float xx = (float)(idx % 7) - 3.f;
            float xr =  xx * ct + yy * st;
            float yr = -xx * st + yy * ct;
            v1 = expf(-(xr * xr * inv1 + yr * yr * inv2));
        }
    }
    float s = v0 + v1;
    for (int off = 16; off; off >>= 1) s += __shfl_xor_sync(0xffffffffu, s, off);
    float inv_sum = 1.f / (s + 1e-8f);
    kern[b * 49 + lane] = v0 * inv_sum;
    if (lane + 32 < 49) kern[b * 49 + lane + 32] = v1 * inv_sum;
}

// ---------------------------------------------------------------------------
// Depthwise 7x7 cross-correlation (zero pad) on the shifted spectrum.
// Each thread: 4 rows x 1 col, loads straight from global (L1 reuse).
// grid: (2048, 16); block 256 (128 cols x 2 row-groups of 4)
// ---------------------------------------------------------------------------
__global__ void __launch_bounds__(256)
conv_kernel(const float* __restrict__ Sr, const float* __restrict__ Si,
            const float* __restrict__ kern,
            float* __restrict__ Cr, float* __restrict__ Ci)
{
    __shared__ float kk[49];
    const int tid = threadIdx.x;
    const int bc  = blockIdx.x;
    const int b   = bc >> 8;
    if (tid < 49) kk[tid] = kern[b * 49 + tid];
    __syncthreads();

    const int tx = tid & 127;
    const int tg = tid >> 7;
    const int y0 = blockIdx.y * 8 + tg * 4;
    const size_t ibase = (size_t)bc * 16384;

    float ar[4] = {0.f, 0.f, 0.f, 0.f};
    float ai[4] = {0.f, 0.f, 0.f, 0.f};

#pragma unroll
    for (int z = 0; z < 10; ++z) {
        int gy = y0 - 3 + z;
        if (gy < 0 || gy >= 128) continue;
        const float* rr = Sr + ibase + (size_t)gy * 128;
        const float* ri = Si + ibase + (size_t)gy * 128;
        float vr[7], vi[7];
#pragma unroll
        for (int s = 0; s < 7; ++s) {
            int gx = tx - 3 + s;
            bool ok = ((unsigned)gx < 128u);
            vr[s] = ok ? rr[gx] : 0.f;
            vi[s] = ok ? ri[gx] : 0.f;
        }
#pragma unroll
        for (int i = 0; i < 4; ++i) {
            int r = z - i;
            if (r < 0 || r > 6) continue;
#pragma unroll
            for (int s = 0; s < 7; ++s) {
                float w = kk[r * 7 + s];
                ar[i] += vr[s] * w;
                ai[i] += vi[s] * w;
            }
        }
    }
#pragma unroll
    for (int i = 0; i < 4; ++i) {
        size_t o = ibase + (size_t)(y0 + i) * 128 + tx;
        Cr[o] = ar[i];
        Ci[o] = ai[i];
    }
}

// ---------------------------------------------------------------------------
// out[b,o,y,x] = sum_c refine[o,c] * Z[b,c,y,x] + bilinear_up(x_high)[b,o,y,x]
// fp32 tiled GEMM: 128(o) x 128(p) x 16 tiles, 8x8 per thread.
// grid: (128 = y rows, 2 = o tiles, 8 = batch), block 256
// ---------------------------------------------------------------------------
__global__ void __launch_bounds__(256)
gemm_kernel(const float* __restrict__ refine, const float* __restrict__ Z,
            const float* __restrict__ xh, float* __restrict__ out)
{
    __shared__ float As[16][132];
    __shared__ float Bs[16][132];

    const int b    = blockIdx.z;
    const int ot   = blockIdx.y;
    const int yrow = blockIdx.x;
    const int tid  = threadIdx.x;
    const int txq  = tid & 15;   // 16 p-groups
    const int tyq  = tid >> 4;   // 16 o-groups

    const float* Zb = Z + (size_t)b * 256 * 16384 + (size_t)yrow * 128;

    float acc[8][8];
#pragma unroll
    for (int i = 0; i < 8; ++i)
#pragma unroll
        for (int j = 0; j < 8; ++j) acc[i][j] = 0.f;

    for (int k0 = 0; k0 < 256; k0 += 16) {
#pragma unroll
        for (int i = 0; i < 8; ++i) {
            int o = (tid >> 4) + i * 16;
            int k = tid & 15;
            As[k][o] = refine[(size_t)(ot * 128 + o) * 256 + k0 + k];
        }
#pragma unroll
        for (int i = 0; i < 2; ++i) {
            int k  = (tid >> 5) + i * 8;
            int x4 = (tid & 31) * 4;
            float4 v = *(const float4*)(Zb + (size_t)(k0 + k) * 16384 + x4);
            *(float4*)&Bs[k][x4] = v;
        }
        __syncthreads();
#pragma unroll
        for (int k = 0; k < 16; ++k) {
            float a[8], bb[8];
#pragma unroll
            for (int i = 0; i < 8; ++i) a[i] = As[k][tyq * 8 + i];
#pragma unroll
            for (int j = 0; j < 8; ++j) bb[j] = Bs[k][txq * 8 + j];
#pragma unroll
            for (int i = 0; i < 8; ++i)
#pragma unroll
                for (int j = 0; j < 8; ++j) acc[i][j] += a[i] * bb[j];
        }
        __syncthreads();
    }

    // bilinear weights for this y row (half-pixel, clamped == renormalized)
    const int y = yrow;
    int ym0, ym1; float wy0, wy1;
    if ((y & 1) == 0) { int u = y >> 1; ym0 = (u > 0) ? u - 1 : 0; ym1 = u; wy0 = 0.25f; wy1 = 0.75f; }
    else              { int u = y >> 1; ym0 = u; ym1 = (u < 63) ? u + 1 : 63; wy0 = 0.75f; wy1 = 0.25f; }

#pragma unroll
    for (int i = 0; i < 8; ++i) {
        int o = ot * 128 + tyq * 8 + i;
        const float* xr0 = xh + ((size_t)(b * 256 + o) * 64 + ym0) * 64;
        const float* xr1 = xh + ((size_t)(b * 256 + o) * 64 + ym1) * 64;
        float* po = out + (size_t)(b * 256 + o) * 16384 + (size_t)y * 128;
#pragma unroll
        for (int j = 0; j < 8; ++j) {
            int x = txq * 8 + j;
            int xm0, xm1; float wx0, wx1;
            if ((x & 1) == 0) { int u = x >> 1; xm0 = (u > 0) ? u - 1 : 0; xm1 = u; wx0 = 0.25f; wx1 = 0.75f; }
            else              { int u = x >> 1; xm0 = u; xm1 = (u < 63) ? u + 1 : 63; wx0 = 0.75f; wx1 = 0.25f; }
            float up = wy0 * (wx0 * xr0[xm0] + wx1 * xr0[xm1])
                     + wy1 * (wx0 * xr1[xm0] + wx1 * xr1[xm1]);
            po[x] = acc[i][j] + up;
        }
    }
}

// ---------------------------------------------------------------------------
// Launch
// ---------------------------------------------------------------------------
extern "C" void kernel_launch(void* const* d_in, const int* in_sizes, int n_in,
                              void* d_out, int out_size)
{
    const float* x_high = (const float*)d_in[0];
    const float* x_low  = (const float*)d_in[1];
    const float* w1     = (const float*)d_in[2];
    const float* b1     = (const float*)d_in[3];
    const float* w2     = (const float*)d_in[4];
    const float* b2     = (const float*)d_in[5];
    const float* refine = (const float*)d_in[6];
    float* out = (float*)d_out;

    float *b0r, *b0i, *b1r_, *b1i_, *magp, *kernp;
    cudaGetSymbolAddress((void**)&b0r,  g_b0r);
    cudaGetSymbolAddress((void**)&b0i,  g_b0i);
    cudaGetSymbolAddress((void**)&b1r_, g_b1r);
    cudaGetSymbolAddress((void**)&b1i_, g_b1i);
    cudaGetSymbolAddress((void**)&magp, g_mag);
    cudaGetSymbolAddress((void**)&kernp, g_kern);

    const int FFT_BLOCKS = NIMG * 4;  // 8192

    // 1) forward FFT rows (x): real input, ortho 1/128, fftshift(x) on store
    //    out: A[b,c][xs][y]
    fft_pass<false, false, true, true, false>
        <<<FFT_BLOCKS, 256>>>(x_low, nullptr, b0r, b0i, 1.f / 128.f);

    // 2) forward FFT cols (y): fftshift(y) on store -> S[b,c][ys][xs]
    fft_pass<false, false, true, false, false>
        <<<FFT_BLOCKS, 256>>>(b0r, b0i, b1r_, b1i_, 1.f);

    // 3) 7x7 center magnitudes (mean over channels)
    mag_kernel<<<8, 256>>>(b1r_, b1i_, magp);

    // 4) MLP + anisotropic kernel per batch
    mlp_kernel<<<1, 256>>>(w1, b1, w2, b2, magp, kernp);

    // 5) depthwise 7x7 conv (zero pad) on shifted spectrum -> Cv[b,c][ys][xs]
    conv_kernel<<<dim3(NIMG, 16), 256>>>(b1r_, b1i_, kernp, b0r, b0i);

    // 6) inverse FFT over x: ifftshift(x) on load, scale 1/128 -> D[b,c][x][ys]
    fft_pass<true, true, false, false, false>
        <<<FFT_BLOCKS, 256>>>(b0r, b0i, b1r_, b1i_, 1.f / 128.f);

    // 7) inverse FFT over y: ifftshift(y) on load, real output -> Z[b,c][y][x]
    fft_pass<true, true, false, false, true>
        <<<FFT_BLOCKS, 256>>>(b1r_, b1i_, b0r, nullptr, 1.f);

    // 8) channel mix (refine_w) + fused bilinear upsample add
    gemm_kernel<<<dim3(128, 2, 8), 256>>>(refine, b0r, x_high, out);
}

// round 2
// speedup vs baseline: 1.4151x; 1.4151x over previous
#include <cuda_runtime.h>
#include <math.h>

#define NIMG   2048          // B*C
#define PI_F   3.14159265358979323846f

typedef unsigned long long ull;

// Scratch (device globals; allocation-free per harness rules)
__device__ __align__(16) float2 g_buf0[NIMG * 16384];
__device__ __align__(16) float2 g_buf1[NIMG * 16384];
__device__ float g_mag[8 * 49];
__device__ float g_kern[8 * 49];

// ---------------------------------------------------------------------------
// packed f32x2 helpers
// ---------------------------------------------------------------------------
__device__ __forceinline__ ull pk2(float lo, float hi) {
    ull r; asm("mov.b64 %0,{%1,%2};" : "=l"(r) : "f"(lo), "f"(hi)); return r;
}
__device__ __forceinline__ void upk2(ull v, float& lo, float& hi) {
    asm("mov.b64 {%0,%1}, %2;" : "=f"(lo), "=f"(hi) : "l"(v));
}
__device__ __forceinline__ ull fma2(ull a, ull b, ull c) {
    ull d; asm("fma.rn.f32x2 %0, %1, %2, %3;" : "=l"(d) : "l"(a), "l"(b), "l"(c));
    return d;
}

// ---------------------------------------------------------------------------
// Register/shuffle 128-point FFT (four-step: radix-4 regs + 32-pt lane FFT)
// Input : x[a] = element (lane + 32a)
// Output: x[c] = X[4*lane + c]
// ---------------------------------------------------------------------------
struct cpx { float r, i; };
__device__ __forceinline__ cpx cadd(cpx a, cpx b){ return {a.r+b.r, a.i+b.i}; }
__device__ __forceinline__ cpx csub(cpx a, cpx b){ return {a.r-b.r, a.i-b.i}; }
__device__ __forceinline__ cpx cmul(cpx a, cpx b){
    return {a.r*b.r - a.i*b.i, a.r*b.i + a.i*b.r};
}

struct Twid {
    cpx w1, w2, w3;        // W128^{l}, ^2l, ^3l
    cpx t16, t8, t4, t2;   // 32-FFT stage twiddles
    int brl;               // bitrev5(lane)
};

template<bool INV>
__device__ __forceinline__ Twid make_twid(int lane) {
    Twid T;
    const float sgn = INV ? 1.f : -1.f;
    float a1 = sgn * (2.f * PI_F / 128.f) * (float)lane;
    __sincosf(a1, &T.w1.i, &T.w1.r);
    T.w2 = cmul(T.w1, T.w1);
    T.w3 = cmul(T.w2, T.w1);
    float ah;
    ah = sgn * PI_F * (float)(lane & 15) / 16.f; __sincosf(ah, &T.t16.i, &T.t16.r);
    ah = sgn * PI_F * (float)(lane & 7)  / 8.f;  __sincosf(ah, &T.t8.i,  &T.t8.r);
    ah = sgn * PI_F * (float)(lane & 3)  / 4.f;  __sincosf(ah, &T.t4.i,  &T.t4.r);
    ah = sgn * PI_F * (float)(lane & 1)  / 2.f;  __sincosf(ah, &T.t2.i,  &T.t2.r);
    T.brl = (int)(__brev((unsigned)lane) >> 27);
    return T;
}

__device__ __forceinline__ cpx shflx(cpx v, int h) {
    cpx o;
    o.r = __shfl_xor_sync(0xffffffffu, v.r, h);
    o.i = __shfl_xor_sync(0xffffffffu, v.i, h);
    return o;
}

__device__ __forceinline__ void bf(cpx& v, int lane, int h, cpx tw, bool usetw) {
    cpx o = shflx(v, h);
    if (lane & h) {
        cpx d = csub(o, v);
        v = usetw ? cmul(d, tw) : d;
    } else {
        v = cadd(v, o);
    }
}

template<bool INV>
__device__ __forceinline__ void fft128(cpx x[4], const Twid& T, int lane) {
    // radix-4 over registers (stride-32 decimation)
    cpx s0 = cadd(x[0], x[2]), d0 = csub(x[0], x[2]);
    cpx s1 = cadd(x[1], x[3]), d1 = csub(x[1], x[3]);
    cpx jd1 = { -d1.i, d1.r };               // +i * d1
    cpx F0 = cadd(s0, s1);
    cpx F2 = csub(s0, s1);
    cpx F1, F3;
    if (INV) { F1 = cadd(d0, jd1); F3 = csub(d0, jd1); }
    else     { F1 = csub(d0, jd1); F3 = cadd(d0, jd1); }
    x[0] = F0;
    x[1] = cmul(F1, T.w1);
    x[2] = cmul(F2, T.w2);
    x[3] = cmul(F3, T.w3);
    // 32-pt DIF across lanes (4 independent sequences)
#pragma unroll
    for (int c = 0; c < 4; ++c) {
        bf(x[c], lane, 16, T.t16, true);
        bf(x[c], lane, 8,  T.t8,  true);
        bf(x[c], lane, 4,  T.t4,  true);
        bf(x[c], lane, 2,  T.t2,  true);
        bf(x[c], lane, 1,  T.t2,  false);
        float rr = __shfl_sync(0xffffffffu, x[c].r, T.brl);
        float ii = __shfl_sync(0xffffffffu, x[c].i, T.brl);
        x[c].r = rr; x[c].i = ii;
    }
}

// ---------------------------------------------------------------------------
// P1: forward FFT over x (real input), fftshift(x) on store, transposed out.
// in : x_low[img][y][x]        out: T1[img][fxs][y]
// CTA = (img, grp of 32 rows), 8 warps x 4 rows
// ---------------------------------------------------------------------------
__global__ void __launch_bounds__(256)
p1_kernel(const float* __restrict__ in, float2* __restrict__ out)
{
    __shared__ float st_r[4096], st_i[4096];
    const int tid = threadIdx.x, warp = tid >> 5, lane = tid & 31;
    const int img = blockIdx.x >> 2, grp = blockIdx.x & 3;
    const size_t ibase = (size_t)img * 16384;
    Twid T = make_twid<false>(lane);

#pragma unroll
    for (int q = 0; q < 4; ++q) {
        int rl = warp * 4 + q;
        int row = grp * 32 + rl;
        const float* p = in + ibase + (size_t)row * 128;
        cpx x[4];
#pragma unroll
        for (int a = 0; a < 4; ++a) x[a] = { p[lane + 32 * a] * (1.f / 128.f), 0.f };
        fft128<false>(x, T, lane);
        int mh = lane ^ 16;                    // fftshift: k^64 = 4*(m^16)+c
#pragma unroll
        for (int c = 0; c < 4; ++c) {
            int fx = 4 * mh + c;
            int s = fx * 32 + (rl ^ mh);
            st_r[s] = x[c].r; st_i[s] = x[c].i;
        }
    }
    __syncthreads();
    const int g0 = grp * 32;
#pragma unroll
    for (int it = 0; it < 16; ++it) {
        int idx = it * 256 + tid;
        int f = idx >> 5, rl = idx & 31;
        int s = f * 32 + (rl ^ (f >> 2));
        out[ibase + (size_t)f * 128 + (g0 + rl)] = make_float2(st_r[s], st_i[s]);
    }
}

// ---------------------------------------------------------------------------
// P2: forward FFT over y, fftshift(y) on store, DIRECT store (contiguous).
// in: T1[img][fxs][y]   out: S[img][fxs][fys]
// ---------------------------------------------------------------------------
__global__ void __launch_bounds__(256)
p2_kernel(const float2* __restrict__ in, float2* __restrict__ out)
{
    const int tid = threadIdx.x, warp = tid >> 5, lane = tid & 31;
    const int img = blockIdx.x >> 2, grp = blockIdx.x & 3;
    const size_t ibase = (size_t)img * 16384;
    Twid T = make_twid<false>(lane);

#pragma unroll
    for (int q = 0; q < 4; ++q) {
        int row = grp * 32 + warp * 4 + q;
        const float2* p = in + ibase + (size_t)row * 128;
        cpx x[4];
#pragma unroll
        for (int a = 0; a < 4; ++a) { float2 v = p[lane + 32 * a]; x[a] = { v.x, v.y }; }
        fft128<false>(x, T, lane);
        float2* o = out + ibase + (size_t)row * 128;
        int mh = lane ^ 16;
        float4 v0 = make_float4(x[0].r, x[0].i, x[1].r, x[1].i);
        float4 v1 = make_float4(x[2].r, x[2].i, x[3].r, x[3].i);
        *(float4*)(o + 4 * mh)     = v0;
        *(float4*)(o + 4 * mh + 2) = v1;
    }
}

// ---------------------------------------------------------------------------
// mag: mean over 256 channels of |S| at center 7x7. Block = (b, i).
// S layout [img][xs][ys]: point (dy,dx) -> S[.. (61+dx)*128 + (61+dy)]
// ---------------------------------------------------------------------------
__global__ void __launch_bounds__(256)
mag_kernel(const float2* __restrict__ S, float* __restrict__ mag)
{
    __shared__ float red[256];
    const int bi = blockIdx.x;
    const int b = bi / 49, i = bi % 49;
    const int dy = i / 7, dx = i % 7;
    const int c = threadIdx.x;
    float2 v = S[(size_t)(b * 256 + c) * 16384 + (size_t)(61 + dx) * 128 + (61 + dy)];
    red[c] = sqrtf(v.x * v.x + v.y * v.y);
    __syncthreads();
    for (int s = 128; s > 0; s >>= 1) {
        if (c < s) red[c] += red[c + s];
        __syncthreads();
    }
    if (c == 0) mag[b * 49 + i] = red[0] * (1.f / 256.f);
}

// ---------------------------------------------------------------------------
// MLP (49->32->3) + anisotropic kernel generation. One warp per batch.
// ---------------------------------------------------------------------------
__global__ void __launch_bounds__(256)
mlp_kernel(const float* __restrict__ w1, const float* __restrict__ b1,
           const float* __restrict__ w2, const float* __restrict__ b2,
           const float* __restrict__ mag, float* __restrict__ kern)
{
    const int tid = threadIdx.x;
    const int b = tid >> 5;
    const int lane = tid & 31;
    __shared__ float sh_h[8][32];
    __shared__ float sp[8][3];

    float h = b1[lane];
    for (int i = 0; i < 49; ++i) h += mag[b * 49 + i] * w1[lane * 49 + i];
    h = fmaxf(h, 0.f);
    sh_h[b][lane] = h;
    __syncthreads();

    if (lane < 3) {
        float p = b2[lane];
        for (int j = 0; j < 32; ++j) p += sh_h[b][j] * w2[lane * 32 + j];
        sp[b][lane] = p;
    }
    __syncthreads();

    float p0 = sp[b][0], p1 = sp[b][1], p2 = sp[b][2];
    float theta = atan2f(p0, p1) * 0.5f + PI_F * 0.5f;
    float lam1  = expf(p2);
    float lam2  = 1.f / (lam1 + 1e-8f);
    float ct = cosf(theta), st = sinf(theta);
    float inv1 = 1.f / (2.f * lam1 * lam1);
    float inv2 = 1.f / (2.f * lam2 * lam2);

    float v0 = 0.f, v1 = 0.f;
    {
        int idx = lane;
        float yy = (float)(idx / 7) - 3.f;
        float xx = (float)(idx % 7) - 3.f;
        float xr =  xx * ct + yy * st;
        float yr = -xx * st + yy * ct;
        v0 = expf(-(xr * xr * inv1 + yr * yr * inv2));
    }
    {
        int idx = lane + 32;
        if (idx < 49) {
            float yy = (float)(idx / 7) - 3.f;
            float xx = (float)(idx % 7) - 3.f;
            float xr =  xx * ct + yy * st;
            float yr = -xx * st + yy * ct;
            v1 = expf(-(xr * xr * inv1 + yr * yr * inv2));
        }
    }
    float s = v0 + v1;
    for (int off = 16; off; off >>= 1) s += __shfl_xor_sync(0xffffffffu, s, off);
    float inv_sum = 1.f / (s + 1e-8f);
    kern[b * 49 + lane] = v0 * inv_sum;
    if (lane + 32 < 49) kern[b * 49 + lane + 32] = v1 * inv_sum;
}

// ---------------------------------------------------------------------------
// K1: depthwise 7x7 conv on S (packed f32x2) + inverse FFT over ys
//     (ifftshift on load) + transposed store.
// in : S[img][xs][ys]      out: D[img][y][xs]
// CTA = (img, grp of 16 xs rows)
// conv weight for (axis0 off s0, axis1 off s1) = k[s1][s0]
// ---------------------------------------------------------------------------
__global__ void __launch_bounds__(256)
k1_kernel(const float2* __restrict__ S, const float* __restrict__ kern,
          float2* __restrict__ D)
{
    __shared__ float2 Cbuf[16 * 128];   // conv result [x0l][ys], reused as staging
    __shared__ ull kk2[49];
    const int tid = threadIdx.x;
    const int img = blockIdx.x >> 3, grp = blockIdx.x & 7;
    const int b = img >> 8;
    if (tid < 49) { float w = kern[b * 49 + tid]; kk2[tid] = pk2(w, w); }
    __syncthreads();

    // ---- conv phase: thread (ty, tg) computes 8 outputs along axis0 ----
    {
        const int ty = tid & 127;
        const int tg = tid >> 7;
        const int x0base = grp * 16 + tg * 8;
        const float2* Sb = S + (size_t)img * 16384;
        ull acc[8];
#pragma unroll
        for (int i = 0; i < 8; ++i) acc[i] = pk2(0.f, 0.f);
#pragma unroll
        for (int z = 0; z < 14; ++z) {
            int gx = x0base - 3 + z;
            if (gx < 0 || gx >= 128) continue;
            const float2* row = Sb + (size_t)gx * 128;
            ull v[7];
#pragma unroll
            for (int s = 0; s < 7; ++s) {
                int gy = ty - 3 + s;
                float2 t = ((unsigned)gy < 128u) ? row[gy] : make_float2(0.f, 0.f);
                v[s] = pk2(t.x, t.y);
            }
#pragma unroll
            for (int i = 0; i < 8; ++i) {
                int rz = z - i;               // axis0 kernel offset
                if (rz < 0 || rz > 6) continue;
#pragma unroll
                for (int s = 0; s < 7; ++s)   // axis1 kernel offset
                    acc[i] = fma2(v[s], kk2[s * 7 + rz], acc[i]);
            }
        }
#pragma unroll
        for (int i = 0; i < 8; ++i) {
            float lo, hi; upk2(acc[i], lo, hi);
            Cbuf[(tg * 8 + i) * 128 + ty] = make_float2(lo, hi);
        }
    }
    __syncthreads();

    // ---- preload FFT inputs (2 rows per warp), then reuse Cbuf as staging ----
    const int warp = tid >> 5, lane = tid & 31;
    Twid T = make_twid<true>(lane);
    cpx xr[2][4];
#pragma unroll
    for (int q = 0; q < 2; ++q) {
        int rl = warp * 2 + q;
#pragma unroll
        for (int a = 0; a < 4; ++a) {
            float2 v = Cbuf[rl * 128 + ((lane + 32 * a) ^ 64)];   // ifftshift(ys)
            xr[q][a].r = v.x * (1.f / 128.f);
            xr[q][a].i = v.y * (1.f / 128.f);
        }
    }
    __syncthreads();

    float* st_r = (float*)Cbuf;          // staging: [t][x0l], split r/i planes
    float* st_i = st_r + 2048;
#pragma unroll
    for (int q = 0; q < 2; ++q) {
        int rl = warp * 2 + q;
        cpx x[4];
#pragma unroll
        for (int a = 0; a < 4; ++a) x[a] = xr[q][a];
        fft128<true>(x, T, lane);
#pragma unroll
        for (int c = 0; c < 4; ++c) {
            int t = 4 * lane + c;
            int s = t * 16 + (rl ^ (lane & 15));
            st_r[s] = x[c].r;
            st_i[s] = x[c].i;
        }
    }
    __syncthreads();

    const int g0 = grp * 16;
    float2* Do = D + (size_t)img * 16384;
#pragma unroll
    for (int it = 0; it < 8; ++it) {
        int idx = it * 256 + tid;         // 0..2047
        int t = idx >> 4, rl = idx & 15;
        int s = t * 16 + (rl ^ ((t >> 2) & 15));
        Do[(size_t)t * 128 + (g0 + rl)] = make_float2(st_r[s], st_i[s]);
    }
}

// ---------------------------------------------------------------------------
// K2: inverse FFT over xs (ifftshift on load), real output, direct store.
// in: D[img][y][xs]   out: Z[img][y][x] (float)
// ---------------------------------------------------------------------------
__global__ void __launch_bounds__(256)
k2_kernel(const float2* __restrict__ Din, float* __restrict__ Z)
{
    const int tid = threadIdx.x, warp = tid >> 5, lane = tid & 31;
    const int img = blockIdx.x >> 2, grp = blockIdx.x & 3;
    const size_t ibase = (size_t)img * 16384;
    Twid T = make_twid<true>(lane);

#pragma unroll
    for (int q = 0; q < 4; ++q) {
        int row = grp * 32 + warp * 4 + q;
        const float2* pr = Din + ibase + (size_t)row * 128;
        cpx x[4];
#pragma unroll
        for (int a = 0; a < 4; ++a) {
            float2 v = pr[(lane + 32 * a) ^ 64];   // ifftshift(xs)
            x[a].r = v.x; x[a].i = v.y;
        }
        fft128<true>(x, T, lane);
        float4 v = make_float4(x[0].r, x[1].r, x[2].r, x[3].r);
        *(float4*)(Z + ibase + (size_t)row * 128 + 4 * lane) = v;
    }
}

// ---------------------------------------------------------------------------
// out[b,o,y,x] = sum_c refine[o,c] * Z[b,c,y,x] + bilinear_up(x_high)
// fp32 tiled GEMM with packed fma.rn.f32x2 (2 FLOP/lane/instr)
// ---------------------------------------------------------------------------
__global__ void __launch_bounds__(256)
gemm_kernel(const float* __restrict__ refine, const float* __restrict__ Z,
            const float* __restrict__ xh, float* __restrict__ out)
{
    __shared__ float As[16][132];
    __shared__ __align__(16) float Bs[16][132];

    const int b    = blockIdx.z;
    const int ot   = blockIdx.y;
    const int yrow = blockIdx.x;
    const int tid  = threadIdx.x;
    const int txq  = tid & 15;
    const int tyq  = tid >> 4;

    const float* Zb = Z + (size_t)b * 256 * 16384 + (size_t)yrow * 128;

    ull acc2[8][4];
#pragma unroll
    for (int i = 0; i < 8; ++i)
#pragma unroll
        for (int j = 0; j < 4; ++j) acc2[i][j] = pk2(0.f, 0.f);

    for (int k0 = 0; k0 < 256; k0 += 16) {
#pragma unroll
        for (int i = 0; i < 8; ++i) {
            int o = (tid >> 4) + i * 16;
            int k = tid & 15;
            As[k][o] = refine[(size_t)(ot * 128 + o) * 256 + k0 + k];
        }
#pragma unroll
        for (int i = 0; i < 2; ++i) {
            int k  = (tid >> 5) + i * 8;
            int x4 = (tid & 31) * 4;
            float4 v = *(const float4*)(Zb + (size_t)(k0 + k) * 16384 + x4);
            *(float4*)&Bs[k][x4] = v;
        }
        __syncthreads();
#pragma unroll
        for (int k = 0; k < 16; ++k) {
            ull a2[8], b2[4];
#pragma unroll
            for (int i = 0; i < 8; ++i) {
                float av = As[k][tyq * 8 + i];
                a2[i] = pk2(av, av);
            }
#pragma unroll
            for (int j = 0; j < 4; ++j) {
                float2 bv = *(const float2*)&Bs[k][txq * 8 + 2 * j];
                b2[j] = pk2(bv.x, bv.y);
            }
#pragma unroll
            for (int i = 0; i < 8; ++i)
#pragma unroll
                for (int j = 0; j < 4; ++j)
                    acc2[i][j] = fma2(a2[i], b2[j], acc2[i][j]);
        }
        __syncthreads();
    }

    // bilinear weights for this y row (scale 2, half-pixel, clamped)
    const int y = yrow;
    int ym0, ym1; float wy0, wy1;
    if ((y & 1) == 0) { int u = y >> 1; ym0 = (u > 0) ? u - 1 : 0; ym1 = u; wy0 = 0.25f; wy1 = 0.75f; }
    else              { int u = y >> 1; ym0 = u; ym1 = (u < 63) ? u + 1 : 63; wy0 = 0.75f; wy1 = 0.25f; }

#pragma unroll
    for (int i = 0; i < 8; ++i) {
        int o = ot * 128 + tyq * 8 + i;
        const float* xr0 = xh + ((size_t)(b * 256 + o) * 64 + ym0) * 64;
        const float* xr1 = xh + ((size_t)(b * 256 + o) * 64 + ym1) * 64;
        float* po = out + (size_t)(b * 256 + o) * 16384 + (size_t)y * 128;
        float accr[8];
#pragma unroll
        for (int j = 0; j < 4; ++j) upk2(acc2[i][j], accr[2 * j], accr[2 * j + 1]);
#pragma unroll
        for (int j = 0; j < 8; ++j) {
            int x = txq * 8 + j;
            int xm0, xm1; float wx0, wx1;
            if ((x & 1) == 0) { int u = x >> 1; xm0 = (u > 0) ? u - 1 : 0; xm1 = u; wx0 = 0.25f; wx1 = 0.75f; }
            else              { int u = x >> 1; xm0 = u; xm1 = (u < 63) ? u + 1 : 63; wx0 = 0.75f; wx1 = 0.25f; }
            float up = wy0 * (wx0 * xr0[xm0] + wx1 * xr0[xm1])
                     + wy1 * (wx0 * xr1[xm0] + wx1 * xr1[xm1]);
            po[x] = accr[j] + up;
        }
    }
}

// ---------------------------------------------------------------------------
// Launch
// ---------------------------------------------------------------------------
extern "C" void kernel_launch(void* const* d_in, const int* in_sizes, int n_in,
                              void* d_out, int out_size)
{
    const float* x_high = (const float*)d_in[0];
    const float* x_low  = (const float*)d_in[1];
    const float* w1     = (const float*)d_in[2];
    const float* b1     = (const float*)d_in[3];
    const float* w2     = (const float*)d_in[4];
    const float* b2     = (const float*)d_in[5];
    const float* refine = (const float*)d_in[6];
    float* out = (float*)d_out;

    float2 *buf0, *buf1;
    float *magp, *kernp;
    cudaGetSymbolAddress((void**)&buf0,  g_buf0);
    cudaGetSymbolAddress((void**)&buf1,  g_buf1);
    cudaGetSymbolAddress((void**)&magp,  g_mag);
    cudaGetSymbolAddress((void**)&kernp, g_kern);

    // 1) fwd FFT over x (real in, 1/128), fftshift(x), out T1[img][fxs][y]
    p1_kernel<<<NIMG * 4, 256>>>(x_low, buf0);

    // 2) fwd FFT over y, fftshift(y), direct store S[img][fxs][fys]
    p2_kernel<<<NIMG * 4, 256>>>(buf0, buf1);

    // 3) center 7x7 magnitude means
    mag_kernel<<<8 * 49, 256>>>(buf1, magp);

    // 4) MLP + anisotropic kernel
    mlp_kernel<<<1, 256>>>(w1, b1, w2, b2, magp, kernp);

    // 5) conv (packed) + inv FFT over ys (ifftshift, 1/128) -> D[img][y][xs]
    k1_kernel<<<NIMG * 8, 256>>>(buf1, kernp, buf0);

    // 6) inv FFT over xs (ifftshift), real out -> Z[img][y][x]
    k2_kernel<<<NIMG * 4, 256>>>(buf0, (float*)buf1);

    // 7) channel mix + fused bilinear upsample add
    gemm_kernel<<<dim3(128, 2, 8), 256>>>(refine, (const float*)buf1, x_high, out);
}